// round 10
// baseline (speedup 1.0000x reference)
#include <cuda_runtime.h>
#include <cuda_bf16.h>
#include <cstdint>

// Problem constants
#define NN      50000
#define IND     128
#define HIDD    256
#define CAP     96      // max in-degree bucket capacity (Poisson(16), max deg ~45)

// Scratch (device globals; allocation-free)
__device__ int   g_is64;
__device__ int   g_cnt[NN];
__device__ int   g_elist[(size_t)NN * CAP];        // src lists bucketed by dst
// u in bf16, fragment-permuted: per node 64 words; within each 16-k group the
// 8 words are ordered [w0,w4,w1,w5,w2,w6,w3,w7] so an mma A-fragment pair
// {a0,a2} (and {a1,a3}) is one aligned 8-byte load.
__device__ unsigned int g_uhi[(size_t)NN * 64];
__device__ unsigned int g_ulo[(size_t)NN * 64];
// W1 split, [n][k] bf16 with the same per-16k permutation: {b0,b1} = one LDG.64
__device__ unsigned int g_Bhi[256 * 64];
__device__ unsigned int g_Blo[256 * 64];
__device__ float g_y[(size_t)NN * 2];              // h1 @ W2 (atomic, 2 adds/elem)

__device__ __forceinline__ unsigned pack_bf16(float lo, float hi) {
    unsigned short a = __bfloat16_as_ushort(__float2bfloat16_rn(lo));
    unsigned short b = __bfloat16_as_ushort(__float2bfloat16_rn(hi));
    return ((unsigned)b << 16) | (unsigned)a;
}

// ---------------------------------------------------------------------------
// K0: zero counts + zero y + detect int64 vs int32 edge_index
// ---------------------------------------------------------------------------
__global__ void k_init(const int* __restrict__ ei, int nNodes) {
    int i = blockIdx.x * blockDim.x + threadIdx.x;
    if (i < nNodes) {
        g_cnt[i] = 0;
        g_y[2 * i]     = 0.f;
        g_y[2 * i + 1] = 0.f;
    }
    if (blockIdx.x == 0 && threadIdx.x < 32) {
        int w = ei[2 * threadIdx.x + 1];
        unsigned nz = __ballot_sync(0xffffffffu, w != 0);
        if (threadIdx.x == 0) g_is64 = (nz == 0u) ? 1 : 0;
    }
}

// ---------------------------------------------------------------------------
// K1: build per-dst adjacency buckets (int atomics only)
// ---------------------------------------------------------------------------
__global__ void k_build(const int* __restrict__ ei, int E) {
    int e = blockIdx.x * blockDim.x + threadIdx.x;
    if (e >= E) return;
    int src, dst;
    if (g_is64) {
        const int2* ei2 = (const int2*)ei;
        src = ei2[e].x;
        dst = ei2[E + e].x;
    } else {
        src = ei[e];
        dst = ei[E + e];
    }
    int p = atomicAdd(&g_cnt[dst], 1);
    if (p < CAP) g_elist[(size_t)dst * CAP + p] = src;
}

// ---------------------------------------------------------------------------
// K2: layer-1 aggregation (gather) -> bf16 hi/lo in fragment-permuted layout
// warp per node, one float4 per lane (k = 4*lane .. 4*lane+3)
// ---------------------------------------------------------------------------
__global__ void __launch_bounds__(256) k_agg1(const float* __restrict__ x,
                                              const float* __restrict__ eps1p,
                                              int nNodes) {
    int warp = (blockIdx.x * blockDim.x + threadIdx.x) >> 5;
    int lane = threadIdx.x & 31;
    if (warp >= nNodes) return;
    const float4* __restrict__ xv = (const float4*)x;
    float s1 = 1.0f + *eps1p;
    float4 a = xv[(size_t)warp * 32 + lane];
    float4 acc;
    acc.x = s1 * a.x; acc.y = s1 * a.y; acc.z = s1 * a.z; acc.w = s1 * a.w;

    int deg = g_cnt[warp]; if (deg > CAP) deg = CAP;
    const int* __restrict__ lst = &g_elist[(size_t)warp * CAP];
    int e = 0;
    for (; e + 4 <= deg; e += 4) {
        int i0 = lst[e], i1 = lst[e + 1], i2 = lst[e + 2], i3 = lst[e + 3];
        float4 v0 = xv[(size_t)i0 * 32 + lane];
        float4 v1 = xv[(size_t)i1 * 32 + lane];
        float4 v2 = xv[(size_t)i2 * 32 + lane];
        float4 v3 = xv[(size_t)i3 * 32 + lane];
        acc.x += v0.x + v1.x + v2.x + v3.x;
        acc.y += v0.y + v1.y + v2.y + v3.y;
        acc.z += v0.z + v1.z + v2.z + v3.z;
        acc.w += v0.w + v1.w + v2.w + v3.w;
    }
    for (; e < deg; e++) {
        float4 v = xv[(size_t)lst[e] * 32 + lane];
        acc.x += v.x; acc.y += v.y; acc.z += v.z; acc.w += v.w;
    }
    // split fp32 -> bf16 hi + bf16 lo residual
    __nv_bfloat16 hx = __float2bfloat16_rn(acc.x), hy = __float2bfloat16_rn(acc.y);
    __nv_bfloat16 hz = __float2bfloat16_rn(acc.z), hw = __float2bfloat16_rn(acc.w);
    float lx = acc.x - __bfloat162float(hx), ly = acc.y - __bfloat162float(hy);
    float lz = acc.z - __bfloat162float(hz), lw = acc.w - __bfloat162float(hw);
    unsigned h0 = ((unsigned)__bfloat16_as_ushort(hy) << 16) | __bfloat16_as_ushort(hx);
    unsigned h1 = ((unsigned)__bfloat16_as_ushort(hw) << 16) | __bfloat16_as_ushort(hz);
    unsigned l0 = pack_bf16(lx, ly);
    unsigned l1 = pack_bf16(lz, lw);
    // permuted positions: orig word w -> pos = (w<4) ? 2w : 2(w-4)+1
    int kg = lane >> 2;           // 16-k group
    int w0 = 2 * (lane & 3);      // orig word within group (even), w1 = w0+1
    int p0 = (w0 < 4) ? (2 * w0) : (2 * (w0 - 4) + 1);
    int w1 = w0 + 1;
    int p1 = (w1 < 4) ? (2 * w1) : (2 * (w1 - 4) + 1);
    size_t base = (size_t)warp * 64 + kg * 8;
    g_uhi[base + p0] = h0; g_uhi[base + p1] = h1;
    g_ulo[base + p0] = l0; g_ulo[base + p1] = l1;
}

// ---------------------------------------------------------------------------
// K_prep: W1 [k][n] -> Bhi/Blo [n][k] bf16, fragment-permuted.
// Thread per (n, kg, tc): writes uint2 = {word(k=kg*16+tc*2), word(k=...+8)}
// ---------------------------------------------------------------------------
__global__ void k_prep(const float* __restrict__ W1) {
    int L = blockIdx.x * blockDim.x + threadIdx.x;
    if (L >= 256 * 8 * 4) return;
    int n  = L >> 5;
    int kg = (L >> 2) & 7;
    int tc = L & 3;
    int k0 = kg * 16 + tc * 2;
    int k2 = k0 + 8;
    float w00 = W1[(size_t)k0 * 256 + n];
    float w01 = W1[(size_t)(k0 + 1) * 256 + n];
    float w20v = W1[(size_t)k2 * 256 + n];
    float w21v = W1[(size_t)(k2 + 1) * 256 + n];
    __nv_bfloat16 h00 = __float2bfloat16_rn(w00), h01 = __float2bfloat16_rn(w01);
    __nv_bfloat16 h20 = __float2bfloat16_rn(w20v), h21 = __float2bfloat16_rn(w21v);
    unsigned hiA = ((unsigned)__bfloat16_as_ushort(h01) << 16) | __bfloat16_as_ushort(h00);
    unsigned hiB = ((unsigned)__bfloat16_as_ushort(h21) << 16) | __bfloat16_as_ushort(h20);
    unsigned loA = pack_bf16(w00 - __bfloat162float(h00), w01 - __bfloat162float(h01));
    unsigned loB = pack_bf16(w20v - __bfloat162float(h20), w21v - __bfloat162float(h21));
    int u2 = n * 32 + kg * 4 + tc;
    ((uint2*)g_Bhi)[u2] = make_uint2(hiA, hiB);
    ((uint2*)g_Blo)[u2] = make_uint2(loA, loB);
}

// ---------------------------------------------------------------------------
// K3: smem-staged HMMA GEMM, k32 double-buffered stages, 2 CTAs/SM.
// Tile 128 rows x 128 cols (grid (391, 2)), 256 thr = 8 warps:
// warpM = wid&3 (32 rows), warpN = wid>>2 (64 cols).
// 12 stages of K=32 (2 k-steps). smem uint2-slot swizzle: slot^((row&2)<<1)
// -> all LDS.64 / STS.128 conflict-free.
// Epilogue: bias+ReLU, project onto W2, atomicAdd partial y (2 adds/elem,
// order-independent => deterministic).
// ---------------------------------------------------------------------------
__global__ void __launch_bounds__(256, 2) k_gemm_mma(
    const float* __restrict__ b1, const float* __restrict__ W2, int nNodes) {

    __shared__ uint2 sA[2][128][8];
    __shared__ uint2 sB[2][128][8];
    __shared__ float b1s[128], w20s[128], w21s[128];
    __shared__ float red[128][2][2];

    int t = threadIdx.x;
    int wid = t >> 5, lane = t & 31;
    int g = lane >> 2, tc = lane & 3;
    int warpM = wid & 3, warpN = wid >> 2;     // warpN in 0..1
    int rowBase = blockIdx.x * 128;
    int colBase = blockIdx.y * 128;

    if (t < 128) {
        b1s[t]  = b1[colBase + t];
        w20s[t] = W2[2 * (colBase + t)];
        w21s[t] = W2[2 * (colBase + t) + 1];
    }

    // staging indices: thread handles uint4 q of rows srow and srow+64
    int srow = t >> 2;                 // 0..63
    int q    = t & 3;
    int qd   = q ^ (srow & 2);         // swizzled uint4 slot (same for srow+64)
    int arow0 = rowBase + srow;        if (arow0 >= nNodes) arow0 = nNodes - 1;
    int arow1 = rowBase + 64 + srow;   if (arow1 >= nNodes) arow1 = nNodes - 1;
    int nb0 = colBase + srow;
    int nb1 = colBase + 64 + srow;

    const uint4* __restrict__ Ahi4 = (const uint4*)g_uhi;
    const uint4* __restrict__ Alo4 = (const uint4*)g_ulo;
    const uint4* __restrict__ Bhi4 = (const uint4*)g_Bhi;
    const uint4* __restrict__ Blo4 = (const uint4*)g_Blo;

    float acc[2][8][4];
    #pragma unroll
    for (int mt = 0; mt < 2; mt++)
        #pragma unroll
        for (int nt = 0; nt < 8; nt++)
            #pragma unroll
            for (int j = 0; j < 4; j++) acc[mt][nt][j] = 0.f;

    // prologue: stage 0 (phase 0, m = 0)
    {
        uint4* dA = (uint4*)sA[0];
        uint4* dB = (uint4*)sB[0];
        dA[srow * 4 + qd]        = Ahi4[(size_t)arow0 * 16 + q];
        dA[(srow + 64) * 4 + qd] = Ahi4[(size_t)arow1 * 16 + q];
        dB[srow * 4 + qd]        = Bhi4[(size_t)nb0 * 16 + q];
        dB[(srow + 64) * 4 + qd] = Bhi4[(size_t)nb1 * 16 + q];
    }
    __syncthreads();

    // fragment read rows + swizzle terms (row&2 == g&2 for all fragment rows)
    int sw = (g & 2) << 1;    // uint2-slot XOR for reads

    #pragma unroll
    for (int s = 0; s < 12; s++) {
        int buf = s & 1;
        uint4 pa0, pa1, pb0, pb1;
        if (s < 11) {
            int sn = s + 1;
            int p  = sn >> 2;       // phase: 0 uhi*Whi, 1 ulo*Whi, 2 uhi*Wlo
            int m  = sn & 3;
            const uint4* __restrict__ Ap = (p == 1) ? Alo4 : Ahi4;
            const uint4* __restrict__ Bp = (p == 2) ? Blo4 : Bhi4;
            pa0 = Ap[(size_t)arow0 * 16 + m * 4 + q];
            pa1 = Ap[(size_t)arow1 * 16 + m * 4 + q];
            pb0 = Bp[(size_t)nb0 * 16 + m * 4 + q];
            pb1 = Bp[(size_t)nb1 * 16 + m * 4 + q];
        }
        const uint2* __restrict__ cA = &sA[buf][0][0];
        const uint2* __restrict__ cB = &sB[buf][0][0];
        #pragma unroll
        for (int kl = 0; kl < 2; kl++) {
            int slot = (kl * 4 + tc) ^ sw;
            uint2 bf[8];
            #pragma unroll
            for (int nt = 0; nt < 8; nt++) {
                int r = warpN * 64 + nt * 8 + g;
                bf[nt] = cB[r * 8 + slot];
            }
            #pragma unroll
            for (int mt = 0; mt < 2; mt++) {
                int ra = warpM * 32 + mt * 16 + g;
                uint2 aA = cA[ra * 8 + slot];
                uint2 aB = cA[(ra + 8) * 8 + slot];
                #pragma unroll
                for (int nt = 0; nt < 8; nt++) {
                    asm volatile(
                        "mma.sync.aligned.m16n8k16.row.col.f32.bf16.bf16.f32 "
                        "{%0,%1,%2,%3}, {%4,%5,%6,%7}, {%8,%9}, {%0,%1,%2,%3};"
                        : "+f"(acc[mt][nt][0]), "+f"(acc[mt][nt][1]),
                          "+f"(acc[mt][nt][2]), "+f"(acc[mt][nt][3])
                        : "r"(aA.x), "r"(aB.x), "r"(aA.y), "r"(aB.y),
                          "r"(bf[nt].x), "r"(bf[nt].y));
                }
            }
        }
        if (s < 11) {
            uint4* dA = (uint4*)sA[buf ^ 1];
            uint4* dB = (uint4*)sB[buf ^ 1];
            dA[srow * 4 + qd]        = pa0;
            dA[(srow + 64) * 4 + qd] = pa1;
            dB[srow * 4 + qd]        = pb0;
            dB[(srow + 64) * 4 + qd] = pb1;
        }
        __syncthreads();
    }

    // Epilogue: relu(acc + b1) -> project onto this col-tile's W2 slice
    float yv[2][2][2];   // [mt][half(row g / g+8)][component]
    #pragma unroll
    for (int mt = 0; mt < 2; mt++)
        #pragma unroll
        for (int h = 0; h < 2; h++) { yv[mt][h][0] = 0.f; yv[mt][h][1] = 0.f; }

    #pragma unroll
    for (int mt = 0; mt < 2; mt++) {
        #pragma unroll
        for (int nt = 0; nt < 8; nt++) {
            int n0 = warpN * 64 + nt * 8 + tc * 2;   // local col in [0,128)
            int n1 = n0 + 1;
            float v0 = fmaxf(acc[mt][nt][0] + b1s[n0], 0.f);
            float v1 = fmaxf(acc[mt][nt][1] + b1s[n1], 0.f);
            float v2 = fmaxf(acc[mt][nt][2] + b1s[n0], 0.f);
            float v3 = fmaxf(acc[mt][nt][3] + b1s[n1], 0.f);
            yv[mt][0][0] += v0 * w20s[n0] + v1 * w20s[n1];
            yv[mt][0][1] += v0 * w21s[n0] + v1 * w21s[n1];
            yv[mt][1][0] += v2 * w20s[n0] + v3 * w20s[n1];
            yv[mt][1][1] += v2 * w21s[n0] + v3 * w21s[n1];
        }
    }
    #pragma unroll
    for (int mt = 0; mt < 2; mt++)
        #pragma unroll
        for (int h = 0; h < 2; h++)
            #pragma unroll
            for (int c = 0; c < 2; c++) {
                float v = yv[mt][h][c];
                v += __shfl_xor_sync(0xffffffffu, v, 1);
                v += __shfl_xor_sync(0xffffffffu, v, 2);
                yv[mt][h][c] = v;
            }
    if (tc == 0) {
        #pragma unroll
        for (int mt = 0; mt < 2; mt++)
            #pragma unroll
            for (int h = 0; h < 2; h++) {
                int lrow = warpM * 32 + mt * 16 + h * 8 + g;
                red[lrow][warpN][0] = yv[mt][h][0];
                red[lrow][warpN][1] = yv[mt][h][1];
            }
    }
    __syncthreads();
    if (t < 128) {
        int row = rowBase + t;
        if (row < nNodes) {
            // exactly 2 contributions per element (blockIdx.y = 0,1):
            // fp add of two floats is order-independent => deterministic
            atomicAdd(&g_y[2 * row],     red[t][0][0] + red[t][1][0]);
            atomicAdd(&g_y[2 * row + 1], red[t][0][1] + red[t][1][1]);
        }
    }
}

// ---------------------------------------------------------------------------
// K4: layer-2: out[n] = (1+eps2)*y[n] + b2 + sum_{src->n} y[src]
// ---------------------------------------------------------------------------
__global__ void __launch_bounds__(256) k_agg2(const float* __restrict__ b2,
                                              const float* __restrict__ eps2p,
                                              float* __restrict__ outp,
                                              int nNodes) {
    int n = blockIdx.x * blockDim.x + threadIdx.x;
    if (n >= nNodes) return;
    int deg = g_cnt[n]; if (deg > CAP) deg = CAP;
    const int* __restrict__ lst = &g_elist[(size_t)n * CAP];
    const float2* __restrict__ yv = (const float2*)g_y;
    float a0 = 0.f, a1 = 0.f;
    int e = 0;
    for (; e + 4 <= deg; e += 4) {
        int i0 = lst[e], i1 = lst[e + 1], i2 = lst[e + 2], i3 = lst[e + 3];
        float2 v0 = yv[i0], v1 = yv[i1], v2 = yv[i2], v3 = yv[i3];
        a0 += v0.x + v1.x + v2.x + v3.x;
        a1 += v0.y + v1.y + v2.y + v3.y;
    }
    for (; e < deg; e++) {
        float2 v = yv[lst[e]];
        a0 += v.x; a1 += v.y;
    }
    float e2 = 1.0f + *eps2p;
    float2 yn = yv[n];
    float2 res;
    res.x = fmaf(e2, yn.x, b2[0]) + a0;
    res.y = fmaf(e2, yn.y, b2[1]) + a1;
    ((float2*)outp)[n] = res;
}

// ---------------------------------------------------------------------------
extern "C" void kernel_launch(void* const* d_in, const int* in_sizes, int n_in,
                              void* d_out, int out_size) {
    const float* x     = (const float*)d_in[0];
    const int*   ei    = (const int*)d_in[1];
    const float* W1    = (const float*)d_in[2];
    const float* b1    = (const float*)d_in[3];
    const float* W2    = (const float*)d_in[4];
    const float* b2    = (const float*)d_in[5];
    const float* eps1p = (const float*)d_in[6];
    const float* eps2p = (const float*)d_in[7];
    float* outp = (float*)d_out;

    int nNodes = in_sizes[0] / IND;          // 50000
    int E      = in_sizes[1] / 2;            // 800000 edges

    k_init<<<(nNodes + 255) / 256, 256>>>(ei, nNodes);
    k_prep<<<(256 * 8 * 4 + 255) / 256, 256>>>(W1);
    k_build<<<(E + 255) / 256, 256>>>(ei, E);
    k_agg1<<<(nNodes + 7) / 8, 256>>>(x, eps1p, nNodes);
    dim3 ggrid((nNodes + 127) / 128, 2);
    k_gemm_mma<<<ggrid, 256>>>(b1, W2, nNodes);
    k_agg2<<<(nNodes + 255) / 256, 256>>>(b2, eps2p, outp, nNodes);
}

// round 11
// speedup vs baseline: 1.0616x; 1.0616x over previous
#include <cuda_runtime.h>
#include <cuda_bf16.h>
#include <cstdint>

// Problem constants
#define NN      50000
#define IND     128
#define HIDD    256
#define CAP     96      // max in-degree bucket capacity (Poisson(16), max deg ~45)

// Scratch (device globals; allocation-free)
__device__ int   g_is64;
__device__ int   g_cnt[NN];
__device__ int   g_elist[(size_t)NN * CAP];        // src lists bucketed by dst
// u in bf16, fragment-permuted: per node 64 words; within each 16-k group the
// 8 words are ordered [w0,w4,w1,w5,w2,w6,w3,w7] so an mma A-fragment pair
// {a0,a2} (and {a1,a3}) is one aligned 8-byte load.
__device__ unsigned int g_uhi[(size_t)NN * 64];
__device__ unsigned int g_ulo[(size_t)NN * 64];
// W1 split, [n][k] bf16 with the same per-16k permutation: {b0,b1} = one LDG.64
__device__ unsigned int g_Bhi[256 * 64];
__device__ unsigned int g_Blo[256 * 64];
__device__ float g_y[(size_t)NN * 2];              // h1 @ W2 per node

__device__ __forceinline__ unsigned pack_bf16(float lo, float hi) {
    unsigned short a = __bfloat16_as_ushort(__float2bfloat16_rn(lo));
    unsigned short b = __bfloat16_as_ushort(__float2bfloat16_rn(hi));
    return ((unsigned)b << 16) | (unsigned)a;
}
__device__ __forceinline__ uint32_t smem_u32(const void* p) {
    uint32_t a;
    asm("{ .reg .u64 t; cvta.to.shared.u64 t, %1; cvt.u32.u64 %0, t; }"
        : "=r"(a) : "l"(p));
    return a;
}

// ---------------------------------------------------------------------------
// K0: zero counts + detect int64 vs int32 + prep W1 bf16 split (merged)
// ---------------------------------------------------------------------------
__global__ void k_init_prep(const int* __restrict__ ei,
                            const float* __restrict__ W1, int nNodes) {
    int i = blockIdx.x * blockDim.x + threadIdx.x;
    if (i < nNodes) g_cnt[i] = 0;
    if (blockIdx.x == 0 && threadIdx.x < 32) {
        int w = ei[2 * threadIdx.x + 1];
        unsigned nz = __ballot_sync(0xffffffffu, w != 0);
        if (threadIdx.x == 0) g_is64 = (nz == 0u) ? 1 : 0;
    }
    // W1 [k][n] -> Bhi/Blo [n][k] bf16, fragment-permuted
    if (i < 256 * 8 * 4) {
        int n  = i >> 5;
        int kg = (i >> 2) & 7;
        int tc = i & 3;
        int k0 = kg * 16 + tc * 2;
        int k2 = k0 + 8;
        float w00 = W1[(size_t)k0 * 256 + n];
        float w01 = W1[(size_t)(k0 + 1) * 256 + n];
        float w20v = W1[(size_t)k2 * 256 + n];
        float w21v = W1[(size_t)(k2 + 1) * 256 + n];
        __nv_bfloat16 h00 = __float2bfloat16_rn(w00), h01 = __float2bfloat16_rn(w01);
        __nv_bfloat16 h20 = __float2bfloat16_rn(w20v), h21 = __float2bfloat16_rn(w21v);
        unsigned hiA = ((unsigned)__bfloat16_as_ushort(h01) << 16) | __bfloat16_as_ushort(h00);
        unsigned hiB = ((unsigned)__bfloat16_as_ushort(h21) << 16) | __bfloat16_as_ushort(h20);
        unsigned loA = pack_bf16(w00 - __bfloat162float(h00), w01 - __bfloat162float(h01));
        unsigned loB = pack_bf16(w20v - __bfloat162float(h20), w21v - __bfloat162float(h21));
        int u2 = n * 32 + kg * 4 + tc;
        ((uint2*)g_Bhi)[u2] = make_uint2(hiA, hiB);
        ((uint2*)g_Blo)[u2] = make_uint2(loA, loB);
    }
}

// ---------------------------------------------------------------------------
// K1: build per-dst adjacency buckets (int atomics only)
// ---------------------------------------------------------------------------
__global__ void k_build(const int* __restrict__ ei, int E) {
    int e = blockIdx.x * blockDim.x + threadIdx.x;
    if (e >= E) return;
    int src, dst;
    if (g_is64) {
        const int2* ei2 = (const int2*)ei;
        src = ei2[e].x;
        dst = ei2[E + e].x;
    } else {
        src = ei[e];
        dst = ei[E + e];
    }
    int p = atomicAdd(&g_cnt[dst], 1);
    if (p < CAP) g_elist[(size_t)dst * CAP + p] = src;
}

// ---------------------------------------------------------------------------
// K2: layer-1 aggregation (gather) -> bf16 hi/lo in fragment-permuted layout
// warp per node, one float4 per lane (k = 4*lane .. 4*lane+3)
// ---------------------------------------------------------------------------
__global__ void __launch_bounds__(256) k_agg1(const float* __restrict__ x,
                                              const float* __restrict__ eps1p,
                                              int nNodes) {
    int warp = (blockIdx.x * blockDim.x + threadIdx.x) >> 5;
    int lane = threadIdx.x & 31;
    if (warp >= nNodes) return;
    const float4* __restrict__ xv = (const float4*)x;
    float s1 = 1.0f + *eps1p;
    float4 a = xv[(size_t)warp * 32 + lane];
    float4 acc;
    acc.x = s1 * a.x; acc.y = s1 * a.y; acc.z = s1 * a.z; acc.w = s1 * a.w;

    int deg = g_cnt[warp]; if (deg > CAP) deg = CAP;
    const int* __restrict__ lst = &g_elist[(size_t)warp * CAP];
    int e = 0;
    for (; e + 4 <= deg; e += 4) {
        int i0 = lst[e], i1 = lst[e + 1], i2 = lst[e + 2], i3 = lst[e + 3];
        float4 v0 = xv[(size_t)i0 * 32 + lane];
        float4 v1 = xv[(size_t)i1 * 32 + lane];
        float4 v2 = xv[(size_t)i2 * 32 + lane];
        float4 v3 = xv[(size_t)i3 * 32 + lane];
        acc.x += v0.x + v1.x + v2.x + v3.x;
        acc.y += v0.y + v1.y + v2.y + v3.y;
        acc.z += v0.z + v1.z + v2.z + v3.z;
        acc.w += v0.w + v1.w + v2.w + v3.w;
    }
    for (; e < deg; e++) {
        float4 v = xv[(size_t)lst[e] * 32 + lane];
        acc.x += v.x; acc.y += v.y; acc.z += v.z; acc.w += v.w;
    }
    // split fp32 -> bf16 hi + bf16 lo residual
    __nv_bfloat16 hx = __float2bfloat16_rn(acc.x), hy = __float2bfloat16_rn(acc.y);
    __nv_bfloat16 hz = __float2bfloat16_rn(acc.z), hw = __float2bfloat16_rn(acc.w);
    float lx = acc.x - __bfloat162float(hx), ly = acc.y - __bfloat162float(hy);
    float lz = acc.z - __bfloat162float(hz), lw = acc.w - __bfloat162float(hw);
    unsigned h0 = ((unsigned)__bfloat16_as_ushort(hy) << 16) | __bfloat16_as_ushort(hx);
    unsigned h1 = ((unsigned)__bfloat16_as_ushort(hw) << 16) | __bfloat16_as_ushort(hz);
    unsigned l0 = pack_bf16(lx, ly);
    unsigned l1 = pack_bf16(lz, lw);
    // permuted positions: orig word w -> pos = (w<4) ? 2w : 2(w-4)+1
    int kg = lane >> 2;           // 16-k group
    int w0 = 2 * (lane & 3);      // orig word within group (even), w1 = w0+1
    int p0 = (w0 < 4) ? (2 * w0) : (2 * (w0 - 4) + 1);
    int w1 = w0 + 1;
    int p1 = (w1 < 4) ? (2 * w1) : (2 * (w1 - 4) + 1);
    size_t base = (size_t)warp * 64 + kg * 8;
    g_uhi[base + p0] = h0; g_uhi[base + p1] = h1;
    g_ulo[base + p0] = l0; g_ulo[base + p1] = l1;
}

// ---------------------------------------------------------------------------
// K3: cp.async 3-stage pipelined HMMA GEMM.
// BM=128, BN=256, K_eff=384 (uhi*Whi + ulo*Whi + uhi*Wlo), 512 thr, grid 391.
// 16 warps: warpM = wid&3 (32 rows), warpN = wid>>2 (64 cols).
// 24 k16 stages; stage rows are 32B so LDS.64 fragment reads are bank-
// conflict-free with no swizzle. cp.async depth-2 prefetch covers L2 latency,
// no prefetch registers. Epilogue: bias+ReLU, W2 projection, smem reduce.
// ---------------------------------------------------------------------------
__global__ void __launch_bounds__(512, 1) k_gemm_mma(
    const float* __restrict__ b1, const float* __restrict__ W2, int nNodes) {

    __shared__ uint4 sA4[3 * 256];     // 3 stages x 128 rows x 32B
    __shared__ uint4 sB4[3 * 512];     // 3 stages x 256 rows x 32B
    __shared__ float b1s[256], w20s[256], w21s[256];
    __shared__ float red[128][4][2];

    int t = threadIdx.x;
    int wid = t >> 5, lane = t & 31;
    int g = lane >> 2, tc = lane & 3;
    int warpM = wid & 3, warpN = wid >> 2;
    int rowBase = blockIdx.x * 128;

    for (int i = t; i < 256; i += 512) {
        b1s[i]  = b1[i];
        w20s[i] = W2[2 * i];
        w21s[i] = W2[2 * i + 1];
    }

    // staging thread mapping: B row bn (all threads), A row am (t < 256)
    int bn = t >> 1;            // 0..255
    int q2 = t & 1;
    int am = t >> 1;            // 0..127 for t < 256
    bool doA = (t < 256);
    int garow = rowBase + am; if (garow >= nNodes) garow = nNodes - 1;

    uint32_t sAb = smem_u32(sA4);
    uint32_t sBb = smem_u32(sB4);
    uint32_t dstA0 = sAb + (uint32_t)(am * 2 + q2) * 16;
    uint32_t dstB0 = sBb + (uint32_t)(bn * 2 + q2) * 16;

    const uint4* __restrict__ Ahi4 = (const uint4*)g_uhi;
    const uint4* __restrict__ Alo4 = (const uint4*)g_ulo;
    const uint4* __restrict__ Bhi4 = (const uint4*)g_Bhi;
    const uint4* __restrict__ Blo4 = (const uint4*)g_Blo;

    float acc[2][8][4];
    #pragma unroll
    for (int mt = 0; mt < 2; mt++)
        #pragma unroll
        for (int nt = 0; nt < 8; nt++)
            #pragma unroll
            for (int j = 0; j < 4; j++) acc[mt][nt][j] = 0.f;

    // stage issue: phase p = ks>>3 (0:hi*hi, 1:lo*hi, 2:hi*lo), kg = ks&7
    #define ISSUE_STAGE(ks)  do {                                             \
        int _p = (ks) >> 3, _kg = (ks) & 7, _buf = (ks) % 3;                  \
        const uint4* _Ap = (_p == 1) ? Alo4 : Ahi4;                           \
        const uint4* _Bp = (_p == 2) ? Blo4 : Bhi4;                           \
        if (doA) {                                                            \
            const uint4* _src = _Ap + (size_t)garow * 16 + _kg * 2 + q2;      \
            uint32_t _dst = dstA0 + (uint32_t)_buf * 4096;                    \
            asm volatile("cp.async.cg.shared.global [%0], [%1], 16;"          \
                         :: "r"(_dst), "l"(_src));                            \
        }                                                                     \
        {                                                                     \
            const uint4* _src = _Bp + (size_t)bn * 16 + _kg * 2 + q2;         \
            uint32_t _dst = dstB0 + (uint32_t)_buf * 8192;                    \
            asm volatile("cp.async.cg.shared.global [%0], [%1], 16;"          \
                         :: "r"(_dst), "l"(_src));                            \
        }                                                                     \
        asm volatile("cp.async.commit_group;" ::: "memory");                  \
    } while (0)

    ISSUE_STAGE(0);
    ISSUE_STAGE(1);

    #pragma unroll
    for (int ks = 0; ks < 24; ks++) {
        int buf = ks % 3;
        if (ks < 23)
            asm volatile("cp.async.wait_group 1;" ::: "memory");
        else
            asm volatile("cp.async.wait_group 0;" ::: "memory");
        __syncthreads();
        if (ks + 2 < 24) ISSUE_STAGE(ks + 2);

        const uint2* __restrict__ cA = (const uint2*)sA4 + buf * 512;
        const uint2* __restrict__ cB = (const uint2*)sB4 + buf * 1024;
        uint2 bf[8];
        #pragma unroll
        for (int nt = 0; nt < 8; nt++) {
            int r = warpN * 64 + nt * 8 + g;
            bf[nt] = cB[r * 4 + tc];
        }
        #pragma unroll
        for (int mt = 0; mt < 2; mt++) {
            int ra = warpM * 32 + mt * 16 + g;
            uint2 aA = cA[ra * 4 + tc];          // {a0, a2}
            uint2 aB = cA[(ra + 8) * 4 + tc];    // {a1, a3}
            #pragma unroll
            for (int nt = 0; nt < 8; nt++) {
                asm volatile(
                    "mma.sync.aligned.m16n8k16.row.col.f32.bf16.bf16.f32 "
                    "{%0,%1,%2,%3}, {%4,%5,%6,%7}, {%8,%9}, {%0,%1,%2,%3};"
                    : "+f"(acc[mt][nt][0]), "+f"(acc[mt][nt][1]),
                      "+f"(acc[mt][nt][2]), "+f"(acc[mt][nt][3])
                    : "r"(aA.x), "r"(aB.x), "r"(aA.y), "r"(aB.y),
                      "r"(bf[nt].x), "r"(bf[nt].y));
            }
        }
        __syncthreads();
    }
    #undef ISSUE_STAGE

    // Epilogue: relu(acc + b1) -> project onto W2; accumulate per-row partials
    float yv[2][2][2];   // [mt][half(row g / g+8)][component]
    #pragma unroll
    for (int mt = 0; mt < 2; mt++)
        #pragma unroll
        for (int h = 0; h < 2; h++) { yv[mt][h][0] = 0.f; yv[mt][h][1] = 0.f; }

    #pragma unroll
    for (int mt = 0; mt < 2; mt++) {
        #pragma unroll
        for (int nt = 0; nt < 8; nt++) {
            int n0 = warpN * 64 + nt * 8 + tc * 2;
            int n1 = n0 + 1;
            float v0 = fmaxf(acc[mt][nt][0] + b1s[n0], 0.f);
            float v1 = fmaxf(acc[mt][nt][1] + b1s[n1], 0.f);
            float v2 = fmaxf(acc[mt][nt][2] + b1s[n0], 0.f);
            float v3 = fmaxf(acc[mt][nt][3] + b1s[n1], 0.f);
            yv[mt][0][0] += v0 * w20s[n0] + v1 * w20s[n1];
            yv[mt][0][1] += v0 * w21s[n0] + v1 * w21s[n1];
            yv[mt][1][0] += v2 * w20s[n0] + v3 * w20s[n1];
            yv[mt][1][1] += v2 * w21s[n0] + v3 * w21s[n1];
        }
    }
    // reduce across the 4 col-threads (same rows): lanes differing in bits 0,1
    #pragma unroll
    for (int mt = 0; mt < 2; mt++)
        #pragma unroll
        for (int h = 0; h < 2; h++)
            #pragma unroll
            for (int c = 0; c < 2; c++) {
                float v = yv[mt][h][c];
                v += __shfl_xor_sync(0xffffffffu, v, 1);
                v += __shfl_xor_sync(0xffffffffu, v, 2);
                yv[mt][h][c] = v;
            }
    if (tc == 0) {
        #pragma unroll
        for (int mt = 0; mt < 2; mt++)
            #pragma unroll
            for (int h = 0; h < 2; h++) {
                int lrow = warpM * 32 + mt * 16 + h * 8 + g;
                red[lrow][warpN][0] = yv[mt][h][0];
                red[lrow][warpN][1] = yv[mt][h][1];
            }
    }
    __syncthreads();
    if (t < 128) {
        int row = rowBase + t;
        if (row < nNodes) {
            float y0 = (red[t][0][0] + red[t][1][0]) + (red[t][2][0] + red[t][3][0]);
            float y1 = (red[t][0][1] + red[t][1][1]) + (red[t][2][1] + red[t][3][1]);
            g_y[2 * row]     = y0;
            g_y[2 * row + 1] = y1;
        }
    }
}

// ---------------------------------------------------------------------------
// K4: layer-2: out[n] = (1+eps2)*y[n] + b2 + sum_{src->n} y[src]
// ---------------------------------------------------------------------------
__global__ void __launch_bounds__(256) k_agg2(const float* __restrict__ b2,
                                              const float* __restrict__ eps2p,
                                              float* __restrict__ outp,
                                              int nNodes) {
    int n = blockIdx.x * blockDim.x + threadIdx.x;
    if (n >= nNodes) return;
    int deg = g_cnt[n]; if (deg > CAP) deg = CAP;
    const int* __restrict__ lst = &g_elist[(size_t)n * CAP];
    const float2* __restrict__ yv = (const float2*)g_y;
    float a0 = 0.f, a1 = 0.f;
    int e = 0;
    for (; e + 4 <= deg; e += 4) {
        int i0 = lst[e], i1 = lst[e + 1], i2 = lst[e + 2], i3 = lst[e + 3];
        float2 v0 = yv[i0], v1 = yv[i1], v2 = yv[i2], v3 = yv[i3];
        a0 += v0.x + v1.x + v2.x + v3.x;
        a1 += v0.y + v1.y + v2.y + v3.y;
    }
    for (; e < deg; e++) {
        float2 v = yv[lst[e]];
        a0 += v.x; a1 += v.y;
    }
    float e2 = 1.0f + *eps2p;
    float2 yn = yv[n];
    float2 res;
    res.x = fmaf(e2, yn.x, b2[0]) + a0;
    res.y = fmaf(e2, yn.y, b2[1]) + a1;
    ((float2*)outp)[n] = res;
}

// ---------------------------------------------------------------------------
extern "C" void kernel_launch(void* const* d_in, const int* in_sizes, int n_in,
                              void* d_out, int out_size) {
    const float* x     = (const float*)d_in[0];
    const int*   ei    = (const int*)d_in[1];
    const float* W1    = (const float*)d_in[2];
    const float* b1    = (const float*)d_in[3];
    const float* W2    = (const float*)d_in[4];
    const float* b2    = (const float*)d_in[5];
    const float* eps1p = (const float*)d_in[6];
    const float* eps2p = (const float*)d_in[7];
    float* outp = (float*)d_out;

    int nNodes = in_sizes[0] / IND;          // 50000
    int E      = in_sizes[1] / 2;            // 800000 edges

    k_init_prep<<<(nNodes + 255) / 256, 256>>>(ei, W1, nNodes);
    k_build<<<(E + 255) / 256, 256>>>(ei, E);
    k_agg1<<<(nNodes + 7) / 8, 256>>>(x, eps1p, nNodes);
    k_gemm_mma<<<(nNodes + 127) / 128, 512>>>(b1, W2, nNodes);
    k_agg2<<<(nNodes + 255) / 256, 256>>>(b2, eps2p, outp, nNodes);
}

// round 13
// speedup vs baseline: 1.0849x; 1.0219x over previous
#include <cuda_runtime.h>
#include <cuda_bf16.h>
#include <cstdint>

// Problem constants
#define NN      50000
#define IND     128
#define HIDD    256
#define CAP     96      // max in-degree bucket capacity (Poisson(16), max deg ~45)

// Scratch (device globals; allocation-free)
__device__ int   g_is64;
__device__ int   g_cnt[NN];
__device__ int   g_elist[(size_t)NN * CAP];        // src lists bucketed by dst
// u in bf16, fragment-permuted: per node 64 words; within each 16-k group the
// 8 words are ordered [w0,w4,w1,w5,w2,w6,w3,w7] so an mma A-fragment pair
// {a0,a2} (and {a1,a3}) is one aligned 8-byte load.
__device__ unsigned int g_uhi[(size_t)NN * 64];
__device__ unsigned int g_ulo[(size_t)NN * 64];
// W1 split, [n][k] bf16 with the same per-16k permutation: {b0,b1} = one LDG.64
__device__ unsigned int g_Bhi[256 * 64];
__device__ unsigned int g_Blo[256 * 64];
__device__ float g_y[(size_t)NN * 2];              // h1 @ W2 per node

__device__ __forceinline__ unsigned pack_bf16(float lo, float hi) {
    unsigned short a = __bfloat16_as_ushort(__float2bfloat16_rn(lo));
    unsigned short b = __bfloat16_as_ushort(__float2bfloat16_rn(hi));
    return ((unsigned)b << 16) | (unsigned)a;
}
__device__ __forceinline__ uint32_t smem_u32(const void* p) {
    uint32_t a;
    asm("{ .reg .u64 t; cvta.to.shared.u64 t, %1; cvt.u32.u64 %0, t; }"
        : "=r"(a) : "l"(p));
    return a;
}

// ---------------------------------------------------------------------------
// K0: zero counts + detect int64 vs int32 + prep W1 bf16 split (merged)
// ---------------------------------------------------------------------------
__global__ void k_init_prep(const int* __restrict__ ei,
                            const float* __restrict__ W1, int nNodes) {
    int i = blockIdx.x * blockDim.x + threadIdx.x;
    if (i < nNodes) g_cnt[i] = 0;
    if (blockIdx.x == 0 && threadIdx.x < 32) {
        int w = ei[2 * threadIdx.x + 1];
        unsigned nz = __ballot_sync(0xffffffffu, w != 0);
        if (threadIdx.x == 0) g_is64 = (nz == 0u) ? 1 : 0;
    }
    // W1 [k][n] -> Bhi/Blo [n][k] bf16, fragment-permuted
    if (i < 256 * 8 * 4) {
        int n  = i >> 5;
        int kg = (i >> 2) & 7;
        int tc = i & 3;
        int k0 = kg * 16 + tc * 2;
        int k2 = k0 + 8;
        float w00 = W1[(size_t)k0 * 256 + n];
        float w01 = W1[(size_t)(k0 + 1) * 256 + n];
        float w20v = W1[(size_t)k2 * 256 + n];
        float w21v = W1[(size_t)(k2 + 1) * 256 + n];
        __nv_bfloat16 h00 = __float2bfloat16_rn(w00), h01 = __float2bfloat16_rn(w01);
        __nv_bfloat16 h20 = __float2bfloat16_rn(w20v), h21 = __float2bfloat16_rn(w21v);
        unsigned hiA = ((unsigned)__bfloat16_as_ushort(h01) << 16) | __bfloat16_as_ushort(h00);
        unsigned hiB = ((unsigned)__bfloat16_as_ushort(h21) << 16) | __bfloat16_as_ushort(h20);
        unsigned loA = pack_bf16(w00 - __bfloat162float(h00), w01 - __bfloat162float(h01));
        unsigned loB = pack_bf16(w20v - __bfloat162float(h20), w21v - __bfloat162float(h21));
        int u2 = n * 32 + kg * 4 + tc;
        ((uint2*)g_Bhi)[u2] = make_uint2(hiA, hiB);
        ((uint2*)g_Blo)[u2] = make_uint2(loA, loB);
    }
}

// ---------------------------------------------------------------------------
// K1: build per-dst adjacency buckets (int atomics only)
// ---------------------------------------------------------------------------
__global__ void k_build(const int* __restrict__ ei, int E) {
    int e = blockIdx.x * blockDim.x + threadIdx.x;
    if (e >= E) return;
    int src, dst;
    if (g_is64) {
        const int2* ei2 = (const int2*)ei;
        src = ei2[e].x;
        dst = ei2[E + e].x;
    } else {
        src = ei[e];
        dst = ei[E + e];
    }
    int p = atomicAdd(&g_cnt[dst], 1);
    if (p < CAP) g_elist[(size_t)dst * CAP + p] = src;
}

// ---------------------------------------------------------------------------
// K2: layer-1 aggregation (gather) -> bf16 hi/lo in fragment-permuted layout
// warp per node, one float4 per lane (k = 4*lane .. 4*lane+3)
// ---------------------------------------------------------------------------
__global__ void __launch_bounds__(256) k_agg1(const float* __restrict__ x,
                                              const float* __restrict__ eps1p,
                                              int nNodes) {
    int warp = (blockIdx.x * blockDim.x + threadIdx.x) >> 5;
    int lane = threadIdx.x & 31;
    if (warp >= nNodes) return;
    const float4* __restrict__ xv = (const float4*)x;
    float s1 = 1.0f + *eps1p;
    float4 a = xv[(size_t)warp * 32 + lane];
    float4 acc;
    acc.x = s1 * a.x; acc.y = s1 * a.y; acc.z = s1 * a.z; acc.w = s1 * a.w;

    int deg = g_cnt[warp]; if (deg > CAP) deg = CAP;
    const int* __restrict__ lst = &g_elist[(size_t)warp * CAP];
    int e = 0;
    for (; e + 4 <= deg; e += 4) {
        int i0 = lst[e], i1 = lst[e + 1], i2 = lst[e + 2], i3 = lst[e + 3];
        float4 v0 = xv[(size_t)i0 * 32 + lane];
        float4 v1 = xv[(size_t)i1 * 32 + lane];
        float4 v2 = xv[(size_t)i2 * 32 + lane];
        float4 v3 = xv[(size_t)i3 * 32 + lane];
        acc.x += v0.x + v1.x + v2.x + v3.x;
        acc.y += v0.y + v1.y + v2.y + v3.y;
        acc.z += v0.z + v1.z + v2.z + v3.z;
        acc.w += v0.w + v1.w + v2.w + v3.w;
    }
    for (; e < deg; e++) {
        float4 v = xv[(size_t)lst[e] * 32 + lane];
        acc.x += v.x; acc.y += v.y; acc.z += v.z; acc.w += v.w;
    }
    // split fp32 -> bf16 hi + bf16 lo residual
    __nv_bfloat16 hx = __float2bfloat16_rn(acc.x), hy = __float2bfloat16_rn(acc.y);
    __nv_bfloat16 hz = __float2bfloat16_rn(acc.z), hw = __float2bfloat16_rn(acc.w);
    float lx = acc.x - __bfloat162float(hx), ly = acc.y - __bfloat162float(hy);
    float lz = acc.z - __bfloat162float(hz), lw = acc.w - __bfloat162float(hw);
    unsigned h0 = ((unsigned)__bfloat16_as_ushort(hy) << 16) | __bfloat16_as_ushort(hx);
    unsigned h1 = ((unsigned)__bfloat16_as_ushort(hw) << 16) | __bfloat16_as_ushort(hz);
    unsigned l0 = pack_bf16(lx, ly);
    unsigned l1 = pack_bf16(lz, lw);
    // permuted positions: orig word w -> pos = (w<4) ? 2w : 2(w-4)+1
    int kg = lane >> 2;           // 16-k group
    int w0 = 2 * (lane & 3);      // orig word within group (even), w1 = w0+1
    int p0 = (w0 < 4) ? (2 * w0) : (2 * (w0 - 4) + 1);
    int w1 = w0 + 1;
    int p1 = (w1 < 4) ? (2 * w1) : (2 * (w1 - 4) + 1);
    size_t base = (size_t)warp * 64 + kg * 8;
    g_uhi[base + p0] = h0; g_uhi[base + p1] = h1;
    g_ulo[base + p0] = l0; g_ulo[base + p1] = l1;
}

// ---------------------------------------------------------------------------
// K3: cp.async pipelined HMMA GEMM with 64x64 warp tiles.
// BM=128, BN=256, K_eff=384 (uhi*Whi + ulo*Whi + uhi*Wlo), 256 thr, grid 391.
// 8 warps: warpM = wid&1 (64 rows), warpN = wid>>1 (64 cols).
// LDS bytes per HMMA = 4 (vs 6 with 32x64 tiles): smem crossbar no longer
// binds. One __syncthreads per stage (trailing sync removed; next stage's
// wait+sync orders compute(ks) before ISSUE(ks+2) overwrites buf (ks-1)%3).
// Stage rows are 32B so all LDS.64 fragment reads are conflict-free unswizzled.
// ---------------------------------------------------------------------------
__global__ void __launch_bounds__(256, 1) k_gemm_mma(
    const float* __restrict__ b1, const float* __restrict__ W2, int nNodes) {

    __shared__ uint4 sA4[3 * 256];     // 3 stages x 128 rows x 32B
    __shared__ uint4 sB4[3 * 512];     // 3 stages x 256 rows x 32B
    __shared__ float b1s[256], w20s[256], w21s[256];
    __shared__ float red[128][4][2];

    int t = threadIdx.x;
    int wid = t >> 5, lane = t & 31;
    int g = lane >> 2, tc = lane & 3;
    int warpM = wid & 1, warpN = wid >> 1;    // warpM 0..1, warpN 0..3
    int rowBase = blockIdx.x * 128;

    b1s[t]  = b1[t];
    w20s[t] = W2[2 * t];
    w21s[t] = W2[2 * t + 1];

    // staging: A row am2 (1 uint4), B row bn (2 uint4)
    int am2 = t >> 1;           // 0..127
    int q2  = t & 1;
    int bn  = t;                // 0..255
    int garow = rowBase + am2; if (garow >= nNodes) garow = nNodes - 1;

    uint32_t sAb = smem_u32(sA4);
    uint32_t sBb = smem_u32(sB4);
    uint32_t dstA0 = sAb + (uint32_t)(am2 * 2 + q2) * 16;
    uint32_t dstB0 = sBb + (uint32_t)(bn * 2) * 16;

    const uint4* __restrict__ Ahi4 = (const uint4*)g_uhi;
    const uint4* __restrict__ Alo4 = (const uint4*)g_ulo;
    const uint4* __restrict__ Bhi4 = (const uint4*)g_Bhi;
    const uint4* __restrict__ Blo4 = (const uint4*)g_Blo;

    float acc[4][8][4];
    #pragma unroll
    for (int mt = 0; mt < 4; mt++)
        #pragma unroll
        for (int nt = 0; nt < 8; nt++)
            #pragma unroll
            for (int j = 0; j < 4; j++) acc[mt][nt][j] = 0.f;

    // stage issue: phase p = ks>>3 (0:hi*hi, 1:lo*hi, 2:hi*lo), kg = ks&7
    #define ISSUE_STAGE(ks)  do {                                             \
        int _p = (ks) >> 3, _kg = (ks) & 7, _buf = (ks) % 3;                  \
        const uint4* _Ap = (_p == 1) ? Alo4 : Ahi4;                           \
        const uint4* _Bp = (_p == 2) ? Blo4 : Bhi4;                           \
        {                                                                     \
            const uint4* _src = _Ap + (size_t)garow * 16 + _kg * 2 + q2;      \
            uint32_t _dst = dstA0 + (uint32_t)_buf * 4096;                    \
            asm volatile("cp.async.cg.shared.global [%0], [%1], 16;"          \
                         :: "r"(_dst), "l"(_src));                            \
        }                                                                     \
        {                                                                     \
            const uint4* _s0 = _Bp + (size_t)bn * 16 + _kg * 2;               \
            uint32_t _d0 = dstB0 + (uint32_t)_buf * 8192;                     \
            asm volatile("cp.async.cg.shared.global [%0], [%1], 16;"          \
                         :: "r"(_d0), "l"(_s0));                              \
            asm volatile("cp.async.cg.shared.global [%0], [%1], 16;"          \
                         :: "r"(_d0 + 16), "l"(_s0 + 1));                     \
        }                                                                     \
        asm volatile("cp.async.commit_group;" ::: "memory");                  \
    } while (0)

    ISSUE_STAGE(0);
    ISSUE_STAGE(1);

    #pragma unroll
    for (int ks = 0; ks < 24; ks++) {
        int buf = ks % 3;
        if (ks < 23)
            asm volatile("cp.async.wait_group 1;" ::: "memory");
        else
            asm volatile("cp.async.wait_group 0;" ::: "memory");
        __syncthreads();
        if (ks + 2 < 24) ISSUE_STAGE(ks + 2);

        const uint2* __restrict__ cA = (const uint2*)sA4 + buf * 512;
        const uint2* __restrict__ cB = (const uint2*)sB4 + buf * 1024;
        uint2 bf[8];
        #pragma unroll
        for (int nt = 0; nt < 8; nt++) {
            int r = warpN * 64 + nt * 8 + g;
            bf[nt] = cB[r * 4 + tc];
        }
        #pragma unroll
        for (int mt = 0; mt < 4; mt++) {
            int ra = warpM * 64 + mt * 16 + g;
            uint2 aA = cA[ra * 4 + tc];          // {a0, a2}
            uint2 aB = cA[(ra + 8) * 4 + tc];    // {a1, a3}
            #pragma unroll
            for (int nt = 0; nt < 8; nt++) {
                asm volatile(
                    "mma.sync.aligned.m16n8k16.row.col.f32.bf16.bf16.f32 "
                    "{%0,%1,%2,%3}, {%4,%5,%6,%7}, {%8,%9}, {%0,%1,%2,%3};"
                    : "+f"(acc[mt][nt][0]), "+f"(acc[mt][nt][1]),
                      "+f"(acc[mt][nt][2]), "+f"(acc[mt][nt][3])
                    : "r"(aA.x), "r"(aB.x), "r"(aA.y), "r"(aB.y),
                      "r"(bf[nt].x), "r"(bf[nt].y));
            }
        }
        // no trailing sync: next iteration's wait+sync orders compute(ks)
        // before ISSUE(ks+2) overwrites buffer (ks-1)%3
    }
    #undef ISSUE_STAGE
    __syncthreads();

    // Epilogue: relu(acc + b1) -> project onto W2; accumulate per-row partials
    float yv[4][2][2];   // [mt][half(row g / g+8)][component]
    #pragma unroll
    for (int mt = 0; mt < 4; mt++)
        #pragma unroll
        for (int h = 0; h < 2; h++) { yv[mt][h][0] = 0.f; yv[mt][h][1] = 0.f; }

    #pragma unroll
    for (int mt = 0; mt < 4; mt++) {
        #pragma unroll
        for (int nt = 0; nt < 8; nt++) {
            int n0 = warpN * 64 + nt * 8 + tc * 2;
            int n1 = n0 + 1;
            float v0 = fmaxf(acc[mt][nt][0] + b1s[n0], 0.f);
            float v1 = fmaxf(acc[mt][nt][1] + b1s[n1], 0.f);
            float v2 = fmaxf(acc[mt][nt][2] + b1s[n0], 0.f);
            float v3 = fmaxf(acc[mt][nt][3] + b1s[n1], 0.f);
            yv[mt][0][0] += v0 * w20s[n0] + v1 * w20s[n1];
            yv[mt][0][1] += v0 * w21s[n0] + v1 * w21s[n1];
            yv[mt][1][0] += v2 * w20s[n0] + v3 * w20s[n1];
            yv[mt][1][1] += v2 * w21s[n0] + v3 * w21s[n1];
        }
    }
    // reduce across the 4 col-threads (same rows): lanes differing in bits 0,1
    #pragma unroll
    for (int mt = 0; mt < 4; mt++)
        #pragma unroll
        for (int h = 0; h < 2; h++)
            #pragma unroll
            for (int c = 0; c < 2; c++) {
                float v = yv[mt][h][c];
                v += __shfl_xor_sync(0xffffffffu, v, 1);
                v += __shfl_xor_sync(0xffffffffu, v, 2);
                yv[mt][h][c] = v;
            }
    if (tc == 0) {
        #pragma unroll
        for (int mt = 0; mt < 4; mt++)
            #pragma unroll
            for (int h = 0; h < 2; h++) {
                int lrow = warpM * 64 + mt * 16 + h * 8 + g;
                red[lrow][warpN][0] = yv[mt][h][0];
                red[lrow][warpN][1] = yv[mt][h][1];
            }
    }
    __syncthreads();
    if (t < 128) {
        int row = rowBase + t;
        if (row < nNodes) {
            float y0 = (red[t][0][0] + red[t][1][0]) + (red[t][2][0] + red[t][3][0]);
            float y1 = (red[t][0][1] + red[t][1][1]) + (red[t][2][1] + red[t][3][1]);
            g_y[2 * row]     = y0;
            g_y[2 * row + 1] = y1;
        }
    }
}

// ---------------------------------------------------------------------------
// K4: layer-2: out[n] = (1+eps2)*y[n] + b2 + sum_{src->n} y[src]
// ---------------------------------------------------------------------------
__global__ void __launch_bounds__(256) k_agg2(const float* __restrict__ b2,
                                              const float* __restrict__ eps2p,
                                              float* __restrict__ outp,
                                              int nNodes) {
    int n = blockIdx.x * blockDim.x + threadIdx.x;
    if (n >= nNodes) return;
    int deg = g_cnt[n]; if (deg > CAP) deg = CAP;
    const int* __restrict__ lst = &g_elist[(size_t)n * CAP];
    const float2* __restrict__ yv = (const float2*)g_y;
    float a0 = 0.f, a1 = 0.f;
    int e = 0;
    for (; e + 4 <= deg; e += 4) {
        int i0 = lst[e], i1 = lst[e + 1], i2 = lst[e + 2], i3 = lst[e + 3];
        float2 v0 = yv[i0], v1 = yv[i1], v2 = yv[i2], v3 = yv[i3];
        a0 += v0.x + v1.x + v2.x + v3.x;
        a1 += v0.y + v1.y + v2.y + v3.y;
    }
    for (; e < deg; e++) {
        float2 v = yv[lst[e]];
        a0 += v.x; a1 += v.y;
    }
    float e2 = 1.0f + *eps2p;
    float2 yn = yv[n];
    float2 res;
    res.x = fmaf(e2, yn.x, b2[0]) + a0;
    res.y = fmaf(e2, yn.y, b2[1]) + a1;
    ((float2*)outp)[n] = res;
}

// ---------------------------------------------------------------------------
extern "C" void kernel_launch(void* const* d_in, const int* in_sizes, int n_in,
                              void* d_out, int out_size) {
    const float* x     = (const float*)d_in[0];
    const int*   ei    = (const int*)d_in[1];
    const float* W1    = (const float*)d_in[2];
    const float* b1    = (const float*)d_in[3];
    const float* W2    = (const float*)d_in[4];
    const float* b2    = (const float*)d_in[5];
    const float* eps1p = (const float*)d_in[6];
    const float* eps2p = (const float*)d_in[7];
    float* outp = (float*)d_out;

    int nNodes = in_sizes[0] / IND;          // 50000
    int E      = in_sizes[1] / 2;            // 800000 edges

    k_init_prep<<<(nNodes + 255) / 256, 256>>>(ei, W1, nNodes);
    k_build<<<(E + 255) / 256, 256>>>(ei, E);
    k_agg1<<<(nNodes + 7) / 8, 256>>>(x, eps1p, nNodes);
    k_gemm_mma<<<(nNodes + 127) / 128, 256>>>(b1, W2, nNodes);
    k_agg2<<<(nNodes + 255) / 256, 256>>>(b2, eps2p, outp, nNodes);
}